// round 9
// baseline (speedup 1.0000x reference)
#include <cuda_runtime.h>
#include <cuda_bf16.h>
#include <cstdint>

// ============================================================
// TernaryLinear on GB300 — sm_103 BASE-target compatible path.
// tcgen05 is unavailable (harness compiles PTX with .target sm_103,
// which rejects all tcgen05.*). Use Ampere-style mma.sync bf16:
//   1) quant_kernel: ternarize weight -> g_t (bf16 {-1,0,1}), g_scale
//   2) split_kernel: x -> g_xhi + g_xlo (bf16 hi/lo, residual ~2^-16)
//   3) gemm_kernel : 128x128 CTA tile, 8 warps (4Mx2N), BK=32,
//      4-stage cp.async pipeline, ldmatrix + mma.m16n8k16 bf16,
//      fp32 register accumulators, epilogue y = acc*scale + bias
// ============================================================

#define B_DIM 4096
#define I_DIM 4096
#define O_DIM 1024

__device__ __align__(128) __nv_bfloat16 g_t[(size_t)O_DIM * I_DIM];     // 8MB
__device__ float g_scale[O_DIM];
__device__ __align__(128) __nv_bfloat16 g_xhi[(size_t)B_DIM * I_DIM];   // 32MB
__device__ __align__(128) __nv_bfloat16 g_xlo[(size_t)B_DIM * I_DIM];   // 32MB

__device__ __forceinline__ uint32_t smem_to_u32(const void* p) {
    uint32_t a;
    asm("{ .reg .u64 t; cvta.to.shared.u64 t, %1; cvt.u32.u64 %0, t; }" : "=r"(a) : "l"(p));
    return a;
}
__device__ __forceinline__ void cp16(uint32_t dst, const void* src) {
    asm volatile("cp.async.cg.shared.global [%0], [%1], 16;" :: "r"(dst), "l"(src) : "memory");
}
__device__ __forceinline__ void cp_commit() {
    asm volatile("cp.async.commit_group;" ::: "memory");
}
__device__ __forceinline__ void ldsm4(uint32_t* r, uint32_t addr) {
    asm volatile("ldmatrix.sync.aligned.m8n8.x4.shared.b16 {%0,%1,%2,%3}, [%4];"
                 : "=r"(r[0]), "=r"(r[1]), "=r"(r[2]), "=r"(r[3]) : "r"(addr));
}
__device__ __forceinline__ void mma16816(float* c, const uint32_t* a, uint32_t b0, uint32_t b1) {
    asm volatile(
        "mma.sync.aligned.m16n8k16.row.col.f32.bf16.bf16.f32 "
        "{%0,%1,%2,%3}, {%4,%5,%6,%7}, {%8,%9}, {%0,%1,%2,%3};"
        : "+f"(c[0]), "+f"(c[1]), "+f"(c[2]), "+f"(c[3])
        : "r"(a[0]), "r"(a[1]), "r"(a[2]), "r"(a[3]), "r"(b0), "r"(b1));
}

// ============================================================
// Kernel 1: ternary quantization, one block per output row
// ============================================================
__global__ void quant_kernel(const float* __restrict__ w) {
    __shared__ float redf[256];
    __shared__ int   redi[256];
    const int o = blockIdx.x;
    const int tid = threadIdx.x;
    const float4* wr = reinterpret_cast<const float4*>(w + (size_t)o * I_DIM);

    float4 v[4];
    float s = 0.f;
#pragma unroll
    for (int q = 0; q < 4; q++) {
        v[q] = wr[tid + 256 * q];
        s += fabsf(v[q].x) + fabsf(v[q].y) + fabsf(v[q].z) + fabsf(v[q].w);
    }
    redf[tid] = s;
    __syncthreads();
    for (int off = 128; off; off >>= 1) {
        if (tid < off) redf[tid] += redf[tid + off];
        __syncthreads();
    }
    const float delta = 0.05f * redf[0] * (1.0f / (float)I_DIM);
    __syncthreads();

    float sk = 0.f;
    int cnt = 0;
    uint2* tt = reinterpret_cast<uint2*>(g_t + (size_t)o * I_DIM);
#pragma unroll
    for (int q = 0; q < 4; q++) {
        float e[4] = {v[q].x, v[q].y, v[q].z, v[q].w};
        unsigned int h[4];
#pragma unroll
        for (int j = 0; j < 4; j++) {
            float a = fabsf(e[j]);
            if (a > delta) {
                sk += a;
                cnt++;
                h[j] = (e[j] > 0.f) ? 0x3F80u : 0xBF80u;  // bf16 +1 / -1
            } else {
                h[j] = 0u;
            }
        }
        uint2 pkt;
        pkt.x = h[0] | (h[1] << 16);
        pkt.y = h[2] | (h[3] << 16);
        tt[tid + 256 * q] = pkt;
    }
    redf[tid] = sk;
    redi[tid] = cnt;
    __syncthreads();
    for (int off = 128; off; off >>= 1) {
        if (tid < off) { redf[tid] += redf[tid + off]; redi[tid] += redi[tid + off]; }
        __syncthreads();
    }
    if (tid == 0) {
        int n = redi[0] > 1 ? redi[0] : 1;
        g_scale[o] = redf[0] / (float)n;
    }
}

// ============================================================
// Kernel 2: split x into hi/lo bf16
// ============================================================
__global__ void split_kernel(const float4* __restrict__ x) {
    const unsigned i = blockIdx.x * blockDim.x + threadIdx.x;
    float4 v = x[i];
    float e[4] = {v.x, v.y, v.z, v.w};
    unsigned int h[4], l[4];
#pragma unroll
    for (int j = 0; j < 4; j++) {
        __nv_bfloat16 hb = __float2bfloat16(e[j]);
        float r = e[j] - __bfloat162float(hb);
        __nv_bfloat16 lb = __float2bfloat16(r);
        h[j] = (unsigned int)__bfloat16_as_ushort(hb);
        l[j] = (unsigned int)__bfloat16_as_ushort(lb);
    }
    uint2 ph, pl;
    ph.x = h[0] | (h[1] << 16); ph.y = h[2] | (h[3] << 16);
    pl.x = l[0] | (l[1] << 16); pl.y = l[2] | (l[3] << 16);
    reinterpret_cast<uint2*>(g_xhi)[i] = ph;
    reinterpret_cast<uint2*>(g_xlo)[i] = pl;
}

// ============================================================
// Kernel 3: mma.sync bf16 GEMM
//   CTA tile 128x128, warp tile 32x64 (4Mx2N warps), BK=32
//   virtual K = 8192 (iters 0..127 hi, 128..255 lo), 4 stages
//   SMEM rows: 32 bf16 (64B) + 16B pad = 80B (conflict-free)
// ============================================================
#define GK_ITERS    256
#define GK_ROWB     80u                        // smem bytes per row
#define GK_AT       (128u * GK_ROWB)           // 10240 per operand tile
#define GK_STAGE    (2u * GK_AT)               // 20480 per stage (A+B)
#define GK_STAGES   4
#define GK_SCALE    (GK_STAGES * GK_STAGE)     // 81920
#define GK_BIAS     (GK_SCALE + 512)
#define GK_SMEM     (GK_BIAS + 512)            // 82944

struct GLoad {
    const __nv_bfloat16* ahi;
    const __nv_bfloat16* alo;
    const __nv_bfloat16* bsrc;
    uint32_t dstA, dstB;   // smem byte addr for chunk row r0 (stage 0)
};

__device__ __forceinline__ void gk_load_stage(const GLoad& g, int i) {
    const uint32_t st = (uint32_t)(i & 3) * GK_STAGE;
    const __nv_bfloat16* a = ((i < 128) ? g.ahi : g.alo) + (size_t)(i & 127) * 32;
    const __nv_bfloat16* b = g.bsrc + (size_t)(i & 127) * 32;
    cp16(g.dstA + st, a);
    cp16(g.dstA + st + 64u * GK_ROWB, a + (size_t)64 * I_DIM);
    cp16(g.dstB + st, b);
    cp16(g.dstB + st + 64u * GK_ROWB, b + (size_t)64 * I_DIM);
    cp_commit();
}

__global__ __launch_bounds__(256, 2)
void gemm_kernel(const float* __restrict__ bias, float* __restrict__ out) {
    extern __shared__ char smem[];
    const uint32_t sb = smem_to_u32(smem);
    const int tid = threadIdx.x;
    const int wid = tid >> 5;
    const int l   = tid & 31;
    const int wm  = wid >> 1;   // 0..3
    const int wn  = wid & 1;    // 0..1

    // scale / bias into SMEM (ordered by first in-loop __syncthreads)
    if (tid < 128) {
        reinterpret_cast<float*>(smem + GK_SCALE)[tid] = g_scale[blockIdx.y * 128 + tid];
    } else {
        reinterpret_cast<float*>(smem + GK_BIAS)[tid - 128] = bias[blockIdx.y * 128 + (tid - 128)];
    }

    // ---- loader geometry: thread t loads 16B chunks t and t+256 of A and B
    const int r0 = tid >> 2;        // row 0..63 (second chunk: +64)
    const int kc = tid & 3;         // 16B chunk within 64B row
    GLoad g;
    g.ahi  = g_xhi + ((size_t)(blockIdx.x * 128 + r0)) * I_DIM + kc * 8;
    g.alo  = g_xlo + ((size_t)(blockIdx.x * 128 + r0)) * I_DIM + kc * 8;
    g.bsrc = g_t   + ((size_t)(blockIdx.y * 128 + r0)) * I_DIM + kc * 8;
    g.dstA = sb + (uint32_t)r0 * GK_ROWB + (uint32_t)kc * 16;
    g.dstB = g.dstA + GK_AT;

    // ---- ldmatrix per-thread byte offsets (within a stage)
    // A (x4, rows0-7/8-15 x k0-7/8-15): lane l -> row l%16, kcol (l/16)*8
    uint32_t aoff[2];
#pragma unroll
    for (int mt = 0; mt < 2; mt++)
        aoff[mt] = (uint32_t)(wm * 32 + mt * 16 + (l & 15)) * GK_ROWB + (uint32_t)((l >> 4) * 8) * 2;
    // B (x4 covers ntiles 2p,2p+1): j=l/8: n = p*16 + (j>>1)*8 + l%8, k = (j&1)*8
    uint32_t boff[4];
#pragma unroll
    for (int p = 0; p < 4; p++) {
        const int j = l >> 3;
        boff[p] = GK_AT +
                  (uint32_t)(wn * 64 + p * 16 + ((j >> 1) * 8) + (l & 7)) * GK_ROWB +
                  (uint32_t)((j & 1) * 8) * 2;
    }

    float c[2][8][4] = {};

    gk_load_stage(g, 0);
    gk_load_stage(g, 1);
    gk_load_stage(g, 2);

    for (int i = 0; i < GK_ITERS; i++) {
        if (i <= GK_ITERS - 3)      asm volatile("cp.async.wait_group 2;" ::: "memory");
        else if (i == GK_ITERS - 2) asm volatile("cp.async.wait_group 1;" ::: "memory");
        else                        asm volatile("cp.async.wait_group 0;" ::: "memory");
        __syncthreads();

        const uint32_t st = sb + (uint32_t)(i & 3) * GK_STAGE;
#pragma unroll
        for (int ks = 0; ks < 2; ks++) {
            uint32_t a[2][4], b[4][4];
#pragma unroll
            for (int mt = 0; mt < 2; mt++) ldsm4(a[mt], st + aoff[mt] + ks * 32);
#pragma unroll
            for (int p = 0; p < 4; p++)    ldsm4(b[p], st + boff[p] + ks * 32);
#pragma unroll
            for (int mt = 0; mt < 2; mt++)
#pragma unroll
                for (int nt = 0; nt < 8; nt++)
                    mma16816(c[mt][nt], a[mt], b[nt >> 1][(nt & 1) * 2], b[nt >> 1][(nt & 1) * 2 + 1]);
        }

        if (i + 3 < GK_ITERS) gk_load_stage(g, i + 3);
    }

    // ---- epilogue: y = acc * scale[col] + bias[col]
    const float* ss = reinterpret_cast<const float*>(smem + GK_SCALE);
    const float* bb = reinterpret_cast<const float*>(smem + GK_BIAS);
#pragma unroll
    for (int mt = 0; mt < 2; mt++) {
        const int mrow = blockIdx.x * 128 + wm * 32 + mt * 16 + (l >> 2);
#pragma unroll
        for (int nt = 0; nt < 8; nt++) {
            const int cn = wn * 64 + nt * 8 + 2 * (l & 3);
            const float s0 = ss[cn], s1 = ss[cn + 1];
            const float b0 = bb[cn], b1 = bb[cn + 1];
            float* p0 = out + (size_t)mrow * O_DIM + blockIdx.y * 128 + cn;
            float2 v0, v1;
            v0.x = fmaf(c[mt][nt][0], s0, b0);
            v0.y = fmaf(c[mt][nt][1], s1, b1);
            v1.x = fmaf(c[mt][nt][2], s0, b0);
            v1.y = fmaf(c[mt][nt][3], s1, b1);
            *reinterpret_cast<float2*>(p0) = v0;
            *reinterpret_cast<float2*>(p0 + (size_t)8 * O_DIM) = v1;
        }
    }
}

// ============================================================
// launch
// ============================================================
extern "C" void kernel_launch(void* const* d_in, const int* in_sizes, int n_in,
                              void* d_out, int out_size) {
    const float* x    = (const float*)d_in[0];  // [4096, 4096]
    const float* w    = (const float*)d_in[1];  // [1024, 4096]
    const float* bias = (const float*)d_in[2];  // [1024]
    float* out        = (float*)d_out;          // [4096, 1024]

    (void)in_sizes; (void)n_in; (void)out_size;

    quant_kernel<<<O_DIM, 256>>>(w);
    split_kernel<<<(B_DIM * I_DIM / 4) / 512, 512>>>((const float4*)x);

    cudaFuncSetAttribute(gemm_kernel, cudaFuncAttributeMaxDynamicSharedMemorySize, GK_SMEM);
    gemm_kernel<<<dim3(32, 8), 256, GK_SMEM>>>(bias, out);
}

// round 12
// speedup vs baseline: 1.0354x; 1.0354x over previous
#include <cuda_runtime.h>
#include <cuda_bf16.h>
#include <cstdint>

// ============================================================
// TernaryLinear on GB300 — sm_103 base-target (no tcgen05).
// mma.sync bf16 path, v2:
//   GEMM: 128x128 CTA tile, 4 warps (2Mx2N), warp tile 64x64,
//   BK=32, 4-stage cp.async pipeline, prefetch issued BEFORE mma
//   (DMA/MMA overlap), ldmatrix + mma.m16n8k16, fp32 accum,
//   epilogue y = acc*scale + bias.
// Round-9 measured baseline (v1, 8 warps): 242.4us, rel_err 8.9e-6.
// ============================================================

#define B_DIM 4096
#define I_DIM 4096
#define O_DIM 1024

__device__ __align__(128) __nv_bfloat16 g_t[(size_t)O_DIM * I_DIM];     // 8MB
__device__ float g_scale[O_DIM];
__device__ __align__(128) __nv_bfloat16 g_xhi[(size_t)B_DIM * I_DIM];   // 32MB
__device__ __align__(128) __nv_bfloat16 g_xlo[(size_t)B_DIM * I_DIM];   // 32MB

__device__ __forceinline__ uint32_t smem_to_u32(const void* p) {
    uint32_t a;
    asm("{ .reg .u64 t; cvta.to.shared.u64 t, %1; cvt.u32.u64 %0, t; }" : "=r"(a) : "l"(p));
    return a;
}
__device__ __forceinline__ void cp16(uint32_t dst, const void* src) {
    asm volatile("cp.async.cg.shared.global [%0], [%1], 16;" :: "r"(dst), "l"(src) : "memory");
}
__device__ __forceinline__ void cp_commit() {
    asm volatile("cp.async.commit_group;" ::: "memory");
}
__device__ __forceinline__ void ldsm4(uint32_t* r, uint32_t addr) {
    asm volatile("ldmatrix.sync.aligned.m8n8.x4.shared.b16 {%0,%1,%2,%3}, [%4];"
                 : "=r"(r[0]), "=r"(r[1]), "=r"(r[2]), "=r"(r[3]) : "r"(addr));
}
__device__ __forceinline__ void mma16816(float* c, const uint32_t* a, uint32_t b0, uint32_t b1) {
    asm volatile(
        "mma.sync.aligned.m16n8k16.row.col.f32.bf16.bf16.f32 "
        "{%0,%1,%2,%3}, {%4,%5,%6,%7}, {%8,%9}, {%0,%1,%2,%3};"
        : "+f"(c[0]), "+f"(c[1]), "+f"(c[2]), "+f"(c[3])
        : "r"(a[0]), "r"(a[1]), "r"(a[2]), "r"(a[3]), "r"(b0), "r"(b1));
}

// ============================================================
// Kernel 1: ternary quantization (unchanged, 9.7us measured)
// ============================================================
__global__ void quant_kernel(const float* __restrict__ w) {
    __shared__ float redf[256];
    __shared__ int   redi[256];
    const int o = blockIdx.x;
    const int tid = threadIdx.x;
    const float4* wr = reinterpret_cast<const float4*>(w + (size_t)o * I_DIM);

    float4 v[4];
    float s = 0.f;
#pragma unroll
    for (int q = 0; q < 4; q++) {
        v[q] = wr[tid + 256 * q];
        s += fabsf(v[q].x) + fabsf(v[q].y) + fabsf(v[q].z) + fabsf(v[q].w);
    }
    redf[tid] = s;
    __syncthreads();
    for (int off = 128; off; off >>= 1) {
        if (tid < off) redf[tid] += redf[tid + off];
        __syncthreads();
    }
    const float delta = 0.05f * redf[0] * (1.0f / (float)I_DIM);
    __syncthreads();

    float sk = 0.f;
    int cnt = 0;
    uint2* tt = reinterpret_cast<uint2*>(g_t + (size_t)o * I_DIM);
#pragma unroll
    for (int q = 0; q < 4; q++) {
        float e[4] = {v[q].x, v[q].y, v[q].z, v[q].w};
        unsigned int h[4];
#pragma unroll
        for (int j = 0; j < 4; j++) {
            float a = fabsf(e[j]);
            if (a > delta) {
                sk += a;
                cnt++;
                h[j] = (e[j] > 0.f) ? 0x3F80u : 0xBF80u;
            } else {
                h[j] = 0u;
            }
        }
        uint2 pkt;
        pkt.x = h[0] | (h[1] << 16);
        pkt.y = h[2] | (h[3] << 16);
        tt[tid + 256 * q] = pkt;
    }
    redf[tid] = sk;
    redi[tid] = cnt;
    __syncthreads();
    for (int off = 128; off; off >>= 1) {
        if (tid < off) { redf[tid] += redf[tid + off]; redi[tid] += redi[tid + off]; }
        __syncthreads();
    }
    if (tid == 0) {
        int n = redi[0] > 1 ? redi[0] : 1;
        g_scale[o] = redf[0] / (float)n;
    }
}

// ============================================================
// Kernel 2: split x into hi/lo bf16 (unchanged)
// ============================================================
__global__ void split_kernel(const float4* __restrict__ x) {
    const unsigned i = blockIdx.x * blockDim.x + threadIdx.x;
    float4 v = x[i];
    float e[4] = {v.x, v.y, v.z, v.w};
    unsigned int h[4], l[4];
#pragma unroll
    for (int j = 0; j < 4; j++) {
        __nv_bfloat16 hb = __float2bfloat16(e[j]);
        float r = e[j] - __bfloat162float(hb);
        __nv_bfloat16 lb = __float2bfloat16(r);
        h[j] = (unsigned int)__bfloat16_as_ushort(hb);
        l[j] = (unsigned int)__bfloat16_as_ushort(lb);
    }
    uint2 ph, pl;
    ph.x = h[0] | (h[1] << 16); ph.y = h[2] | (h[3] << 16);
    pl.x = l[0] | (l[1] << 16); pl.y = l[2] | (l[3] << 16);
    reinterpret_cast<uint2*>(g_xhi)[i] = ph;
    reinterpret_cast<uint2*>(g_xlo)[i] = pl;
}

// ============================================================
// Kernel 3: mma.sync bf16 GEMM v2
//   CTA 128x128, 4 warps (2Mx2N), warp tile 64x64, BK=32
//   virtual K = 8192 (0..127 hi, 128..255 lo), 4 stages
//   SMEM rows: 32 bf16 (64B) + 16B pad = 80B (conflict-free)
// ============================================================
#define GK_ITERS    256
#define GK_ROWB     80u
#define GK_AT       (128u * GK_ROWB)           // 10240 per operand tile
#define GK_STAGE    (2u * GK_AT)               // 20480 per stage
#define GK_STAGES   4
#define GK_SCALE    (GK_STAGES * GK_STAGE)     // 81920
#define GK_BIAS     (GK_SCALE + 512)
#define GK_SMEM     (GK_BIAS + 512)            // 82944

struct GLoad {
    const __nv_bfloat16* ahi;
    const __nv_bfloat16* alo;
    const __nv_bfloat16* bsrc;
    uint32_t dstA, dstB;
};

// 128 threads: thread t -> rows r0, r0+32, r0+64, r0+96 (A and B), 16B chunk kc
__device__ __forceinline__ void gk_load_stage(const GLoad& g, int i) {
    const uint32_t st = (uint32_t)(i & 3) * GK_STAGE;
    const __nv_bfloat16* a = ((i < 128) ? g.ahi : g.alo) + (size_t)(i & 127) * 32;
    const __nv_bfloat16* b = g.bsrc + (size_t)(i & 127) * 32;
#pragma unroll
    for (int q = 0; q < 4; q++) {
        cp16(g.dstA + st + (uint32_t)q * 32u * GK_ROWB, a + (size_t)q * 32 * I_DIM);
        cp16(g.dstB + st + (uint32_t)q * 32u * GK_ROWB, b + (size_t)q * 32 * I_DIM);
    }
    cp_commit();
}

__global__ __launch_bounds__(128, 2)
void gemm_kernel(const float* __restrict__ bias, float* __restrict__ out) {
    extern __shared__ char smem[];
    const uint32_t sb = smem_to_u32(smem);
    const int tid = threadIdx.x;
    const int wid = tid >> 5;
    const int l   = tid & 31;
    const int wm  = wid >> 1;   // 0..1 -> M halves of 64
    const int wn  = wid & 1;    // 0..1 -> N halves of 64

    // scale / bias into SMEM (visible after first in-loop __syncthreads)
    reinterpret_cast<float*>(smem + GK_SCALE)[tid] = g_scale[blockIdx.y * 128 + tid];
    reinterpret_cast<float*>(smem + GK_BIAS)[tid]  = bias[blockIdx.y * 128 + tid];

    // ---- loader geometry
    const int r0 = tid >> 2;        // 0..31
    const int kc = tid & 3;
    GLoad g;
    g.ahi  = g_xhi + ((size_t)(blockIdx.x * 128 + r0)) * I_DIM + kc * 8;
    g.alo  = g_xlo + ((size_t)(blockIdx.x * 128 + r0)) * I_DIM + kc * 8;
    g.bsrc = g_t   + ((size_t)(blockIdx.y * 128 + r0)) * I_DIM + kc * 8;
    g.dstA = sb + (uint32_t)r0 * GK_ROWB + (uint32_t)kc * 16;
    g.dstB = g.dstA + GK_AT;

    // ---- ldmatrix per-thread byte offsets (within a stage)
    // A x4: lane l -> row (l&15), kcol (l>>4)*8;  mt = 16-row tile index
    uint32_t aoff[4];
#pragma unroll
    for (int mt = 0; mt < 4; mt++)
        aoff[mt] = (uint32_t)(wm * 64 + mt * 16 + (l & 15)) * GK_ROWB + (uint32_t)((l >> 4) * 8) * 2;
    // B x4 (pair of 8-wide n tiles): j=l>>3: n = p*16 + (j>>1)*8 + (l&7), k = (j&1)*8
    uint32_t boff[4];
#pragma unroll
    for (int p = 0; p < 4; p++) {
        const int j = l >> 3;
        boff[p] = GK_AT +
                  (uint32_t)(wn * 64 + p * 16 + ((j >> 1) * 8) + (l & 7)) * GK_ROWB +
                  (uint32_t)((j & 1) * 8) * 2;
    }

    float c[4][8][4] = {};

    gk_load_stage(g, 0);
    gk_load_stage(g, 1);
    gk_load_stage(g, 2);

    for (int i = 0; i < GK_ITERS; i++) {
        if (i <= GK_ITERS - 3)      asm volatile("cp.async.wait_group 2;" ::: "memory");
        else if (i == GK_ITERS - 2) asm volatile("cp.async.wait_group 1;" ::: "memory");
        else                        asm volatile("cp.async.wait_group 0;" ::: "memory");
        __syncthreads();

        // prefetch stage i+3 FIRST: slot (i+3)&3's consumers finished at the
        // barrier above, and issuing now overlaps DMA with the MMA block below.
        if (i + 3 < GK_ITERS) gk_load_stage(g, i + 3);

        const uint32_t st = sb + (uint32_t)(i & 3) * GK_STAGE;
#pragma unroll
        for (int ks = 0; ks < 2; ks++) {
            uint32_t a[4][4], b[4][4];
#pragma unroll
            for (int mt = 0; mt < 4; mt++) ldsm4(a[mt], st + aoff[mt] + ks * 32);
#pragma unroll
            for (int p = 0; p < 4; p++)    ldsm4(b[p], st + boff[p] + ks * 32);
#pragma unroll
            for (int mt = 0; mt < 4; mt++)
#pragma unroll
                for (int nt = 0; nt < 8; nt++)
                    mma16816(c[mt][nt], a[mt], b[nt >> 1][(nt & 1) * 2], b[nt >> 1][(nt & 1) * 2 + 1]);
        }
    }

    // ---- epilogue: y = acc * scale[col] + bias[col]
    const float* ss = reinterpret_cast<const float*>(smem + GK_SCALE);
    const float* bb = reinterpret_cast<const float*>(smem + GK_BIAS);
#pragma unroll
    for (int mt = 0; mt < 4; mt++) {
        const int mrow = blockIdx.x * 128 + wm * 64 + mt * 16 + (l >> 2);
#pragma unroll
        for (int nt = 0; nt < 8; nt++) {
            const int cn = wn * 64 + nt * 8 + 2 * (l & 3);
            const float s0 = ss[cn], s1 = ss[cn + 1];
            const float b0 = bb[cn], b1 = bb[cn + 1];
            float* p0 = out + (size_t)mrow * O_DIM + blockIdx.y * 128 + cn;
            float2 v0, v1;
            v0.x = fmaf(c[mt][nt][0], s0, b0);
            v0.y = fmaf(c[mt][nt][1], s1, b1);
            v1.x = fmaf(c[mt][nt][2], s0, b0);
            v1.y = fmaf(c[mt][nt][3], s1, b1);
            *reinterpret_cast<float2*>(p0) = v0;
            *reinterpret_cast<float2*>(p0 + (size_t)8 * O_DIM) = v1;
        }
    }
}

// ============================================================
// launch
// ============================================================
extern "C" void kernel_launch(void* const* d_in, const int* in_sizes, int n_in,
                              void* d_out, int out_size) {
    const float* x    = (const float*)d_in[0];  // [4096, 4096]
    const float* w    = (const float*)d_in[1];  // [1024, 4096]
    const float* bias = (const float*)d_in[2];  // [1024]
    float* out        = (float*)d_out;          // [4096, 1024]

    (void)in_sizes; (void)n_in; (void)out_size;

    quant_kernel<<<O_DIM, 256>>>(w);
    split_kernel<<<(B_DIM * I_DIM / 4) / 512, 512>>>((const float4*)x);

    cudaFuncSetAttribute(gemm_kernel, cudaFuncAttributeMaxDynamicSharedMemorySize, GK_SMEM);
    gemm_kernel<<<dim3(32, 8), 128, GK_SMEM>>>(bias, out);
}